// round 2
// baseline (speedup 1.0000x reference)
#include <cuda_runtime.h>

#define BB 65536
#define DD 8
#define HH 128
#define EE 64

// ---------------- scratch (static device globals; no runtime allocation) ----
__device__ float g_tok[BB * DD * EE];   // [b][d][o]  134 MB
__device__ float g_poolA[BB * EE];      // 16.8 MB
__device__ float g_poolB[BB * EE];

// ---------------- Kernel A: tokens = W3 sin(W2 sin(x*w1+b1)+b2)+b3 ----------
// grid: (18, 8)  block: 512  dynamic smem ~164KB
#define S1 132   // padded row stride for sh1/sh2 (bank-conflict-free)

__global__ __launch_bounds__(512, 1)
void tok_kernel(const float* __restrict__ x,
                const float* __restrict__ w1, const float* __restrict__ b1,
                const float* __restrict__ w2, const float* __restrict__ b2,
                const float* __restrict__ w3, const float* __restrict__ b3)
{
    extern __shared__ float smem[];
    float* sW2t = smem;                 // [h][k] 128*128
    float* sW3t = sW2t + 16384;         // [h][o] 128*64
    float* sh1  = sW3t + 8192;          // 64 x S1
    float* sh2  = sh1 + 64 * S1;        // 64 x S1
    float* sw1c = sh2 + 64 * S1;        // 128
    float* sb1c = sw1c + 128;           // 128
    float* sb2c = sb1c + 128;           // 128
    float* sb3c = sb2c + 128;           // 64
    float* sx   = sb3c + 64;            // 64

    const int d   = blockIdx.y;
    const int tid = threadIdx.x;

    // stage weights (transposed) once per block
    for (int i = tid; i < HH * HH; i += 512) {
        int k = i >> 7, h = i & 127;
        sW2t[h * HH + k] = w2[d * HH * HH + i];
    }
    for (int i = tid; i < EE * HH; i += 512) {
        int o = i >> 7, h = i & 127;
        sW3t[h * EE + o] = w3[d * EE * HH + i];
    }
    if (tid < 128) {
        sw1c[tid] = w1[d * HH + tid];
        sb1c[tid] = b1[d * HH + tid];
        sb2c[tid] = b2[d * HH + tid];
    }
    if (tid < 64) sb3c[tid] = b3[d * EE + tid];
    __syncthreads();

    const int tx  = tid & 31;   // k-group of 4 (covers 128)
    const int ty  = tid >> 5;   // row-group of 4 (covers 64)
    const int tx2 = tid & 15;   // o-group of 4 (covers 64)
    const int ty2 = tid >> 4;   // row-group of 2 (covers 64)

    const int ntiles = BB / 64;
    for (int t = blockIdx.x; t < ntiles; t += gridDim.x) {
        const int r0 = t * 64;
        if (tid < 64) sx[tid] = x[(r0 + tid) * DD + d];
        __syncthreads();

        // h1 = sin(x*w1+b1)
        for (int i = tid; i < 64 * HH; i += 512) {
            int r = i >> 7, h = i & 127;
            sh1[r * S1 + h] = sinf(sx[r] * sw1c[h] + sb1c[h]);
        }
        __syncthreads();

        // GEMM1: h2 = sin(W2 h1 + b2)
        {
            float acc[4][4];
            #pragma unroll
            for (int j = 0; j < 4; j++)
                #pragma unroll
                for (int i = 0; i < 4; i++) acc[j][i] = 0.f;

            const float* a0p = sh1 + (4 * ty) * S1;
            #pragma unroll 4
            for (int h = 0; h < HH; h++) {
                float4 bv = *(const float4*)(sW2t + h * HH + 4 * tx);
                float a0 = a0p[h];
                float a1 = a0p[S1 + h];
                float a2 = a0p[2 * S1 + h];
                float a3 = a0p[3 * S1 + h];
                acc[0][0] += a0 * bv.x; acc[0][1] += a0 * bv.y; acc[0][2] += a0 * bv.z; acc[0][3] += a0 * bv.w;
                acc[1][0] += a1 * bv.x; acc[1][1] += a1 * bv.y; acc[1][2] += a1 * bv.z; acc[1][3] += a1 * bv.w;
                acc[2][0] += a2 * bv.x; acc[2][1] += a2 * bv.y; acc[2][2] += a2 * bv.z; acc[2][3] += a2 * bv.w;
                acc[3][0] += a3 * bv.x; acc[3][1] += a3 * bv.y; acc[3][2] += a3 * bv.z; acc[3][3] += a3 * bv.w;
            }
            #pragma unroll
            for (int j = 0; j < 4; j++) {
                float4 v;
                v.x = sinf(acc[j][0] + sb2c[4 * tx + 0]);
                v.y = sinf(acc[j][1] + sb2c[4 * tx + 1]);
                v.z = sinf(acc[j][2] + sb2c[4 * tx + 2]);
                v.w = sinf(acc[j][3] + sb2c[4 * tx + 3]);
                *(float4*)(sh2 + (4 * ty + j) * S1 + 4 * tx) = v;
            }
        }
        __syncthreads();

        // GEMM2: tokens = W3 h2 + b3  -> global
        {
            float acc2[2][4];
            #pragma unroll
            for (int j = 0; j < 2; j++)
                #pragma unroll
                for (int i = 0; i < 4; i++) acc2[j][i] = sb3c[4 * tx2 + i];

            const float* a0p = sh2 + (2 * ty2) * S1;
            #pragma unroll 4
            for (int h = 0; h < HH; h++) {
                float4 bv = *(const float4*)(sW3t + h * EE + 4 * tx2);
                float a0 = a0p[h];
                float a1 = a0p[S1 + h];
                acc2[0][0] += a0 * bv.x; acc2[0][1] += a0 * bv.y; acc2[0][2] += a0 * bv.z; acc2[0][3] += a0 * bv.w;
                acc2[1][0] += a1 * bv.x; acc2[1][1] += a1 * bv.y; acc2[1][2] += a1 * bv.z; acc2[1][3] += a1 * bv.w;
            }
            #pragma unroll
            for (int j = 0; j < 2; j++) {
                int row = r0 + 2 * ty2 + j;
                float4 v = make_float4(acc2[j][0], acc2[j][1], acc2[j][2], acc2[j][3]);
                *(float4*)(g_tok + (row * DD + d) * EE + 4 * tx2) = v;
            }
        }
        // next-iteration sync#1 doubles as the GEMM2-done barrier
    }
}

// ---------------- MHA kernels: warp per row -------------------------------
#define SQ 68            // padded stride for sq/sk/sv
#define WARP_FLOATS (512 + 3 * 4 * SQ + 64 + 64)   // 1456

template<int QOFF, int KVOFF, bool ACCUM, bool POOLB>
__global__ __launch_bounds__(256, 2)
void mha_kernel(const float* __restrict__ Win, const float* __restrict__ bin,
                const float* __restrict__ Wo,  const float* __restrict__ bo)
{
    extern __shared__ float smem[];
    float* sWqT = smem;                  // [c][e] 64x64
    float* sWkT = sWqT + 4096;
    float* sWvT = sWkT + 4096;
    float* sWoT = sWvT + 4096;
    float* sbin = sWoT + 4096;           // 192
    float* sbo  = sbin + 192;            // 64
    float* swarp = sbo + 64;

    const int tid = threadIdx.x;
    const int w = tid >> 5, l = tid & 31;

    for (int i = tid; i < 4096; i += 256) {
        int e = i >> 6, c = i & 63;
        sWqT[c * 64 + e] = Win[i];
        sWkT[c * 64 + e] = Win[4096 + i];
        sWvT[c * 64 + e] = Win[8192 + i];
        sWoT[c * 64 + e] = Wo[i];
    }
    if (tid < 192) sbin[tid] = bin[tid];
    if (tid < 64)  sbo[tid]  = bo[tid];
    __syncthreads();

    float* stok = swarp + w * WARP_FLOATS;  // 8x64
    float* sq   = stok + 512;               // 4 x SQ
    float* sk   = sq + 4 * SQ;
    float* sv   = sk + 4 * SQ;
    float* satt = sv + 4 * SQ;              // 64
    float* sos  = satt + 64;                // 64

    float* pool = POOLB ? g_poolB : g_poolA;

    for (int r = blockIdx.x * 8 + w; r < BB; r += gridDim.x * 8) {
        // load this row's 8 tokens (512 floats)
        {
            const float4* gsrc = (const float4*)(g_tok + r * (DD * EE));
            float4* dst = (float4*)stok;
            #pragma unroll
            for (int u = 0; u < 4; u++) dst[l + 32 * u] = gsrc[l + 32 * u];
        }
        __syncwarp();

        // projections: lane handles output dims e0=l, e1=l+32, 4 tokens each
        float qa[4][2], ka[4][2], va[4][2];
        #pragma unroll
        for (int i = 0; i < 4; i++) {
            qa[i][0] = sbin[l];        qa[i][1] = sbin[l + 32];
            ka[i][0] = sbin[64 + l];   ka[i][1] = sbin[96 + l];
            va[i][0] = sbin[128 + l];  va[i][1] = sbin[160 + l];
        }
        #pragma unroll 4
        for (int c = 0; c < 64; c++) {
            float wq0 = sWqT[c * 64 + l], wq1 = sWqT[c * 64 + l + 32];
            float wk0 = sWkT[c * 64 + l], wk1 = sWkT[c * 64 + l + 32];
            float wv0 = sWvT[c * 64 + l], wv1 = sWvT[c * 64 + l + 32];
            #pragma unroll
            for (int i = 0; i < 4; i++) {
                float tq = stok[(QOFF + i) * 64 + c];
                float tk = stok[(KVOFF + i) * 64 + c];
                qa[i][0] += wq0 * tq; qa[i][1] += wq1 * tq;
                ka[i][0] += wk0 * tk; ka[i][1] += wk1 * tk;
                va[i][0] += wv0 * tk; va[i][1] += wv1 * tk;
            }
        }
        #pragma unroll
        for (int i = 0; i < 4; i++) {
            sq[i * SQ + l] = qa[i][0]; sq[i * SQ + l + 32] = qa[i][1];
            sk[i * SQ + l] = ka[i][0]; sk[i * SQ + l + 32] = ka[i][1];
            sv[i * SQ + l] = va[i][0]; sv[i * SQ + l + 32] = va[i][1];
        }
        __syncwarp();

        // attention: lane owns combos m=l and m=l+32; m = h*16 + i*4 + j
        float a01[2];
        #pragma unroll
        for (int z = 0; z < 2; z++) {
            int m = l + 32 * z;
            int h = m >> 4, i = (m >> 2) & 3, j = m & 3;
            float dot = 0.f;
            #pragma unroll
            for (int dd2 = 0; dd2 < 16; dd2++)
                dot += sq[i * SQ + h * 16 + dd2] * sk[j * SQ + h * 16 + dd2];
            a01[z] = dot * 0.25f;   // 1/sqrt(16)
        }
        // softmax over j within 4-lane groups
        float m0 = a01[0], m1 = a01[1];
        m0 = fmaxf(m0, __shfl_xor_sync(0xffffffffu, m0, 1));
        m0 = fmaxf(m0, __shfl_xor_sync(0xffffffffu, m0, 2));
        m1 = fmaxf(m1, __shfl_xor_sync(0xffffffffu, m1, 1));
        m1 = fmaxf(m1, __shfl_xor_sync(0xffffffffu, m1, 2));
        float e0 = __expf(a01[0] - m0), e1 = __expf(a01[1] - m1);
        float s0 = e0, s1 = e1;
        s0 += __shfl_xor_sync(0xffffffffu, s0, 1);
        s0 += __shfl_xor_sync(0xffffffffu, s0, 2);
        s1 += __shfl_xor_sync(0xffffffffu, s1, 1);
        s1 += __shfl_xor_sync(0xffffffffu, s1, 2);
        satt[l] = e0 / s0;
        satt[l + 32] = e1 / s1;
        __syncwarp();

        // os[c] = sum_i o[i][c] = sum_j (sum_i w[h_c][i][j]) * v[j][c]
        {
            float os0 = 0.f, os1 = 0.f;
            int h0 = l >> 4;       // head of c0=l
            int h1 = h0 + 2;       // head of c1=l+32
            #pragma unroll
            for (int j = 0; j < 4; j++) {
                float wj0 = satt[h0 * 16 + j] + satt[h0 * 16 + 4 + j] +
                            satt[h0 * 16 + 8 + j] + satt[h0 * 16 + 12 + j];
                float wj1 = satt[h1 * 16 + j] + satt[h1 * 16 + 4 + j] +
                            satt[h1 * 16 + 8 + j] + satt[h1 * 16 + 12 + j];
                os0 += wj0 * sv[j * SQ + l];
                os1 += wj1 * sv[j * SQ + l + 32];
            }
            sos[l] = os0; sos[l + 32] = os1;
        }
        __syncwarp();

        // pooled out-projection: 0.125 * (Wo * os + 4*bo)
        float p0 = 4.f * sbo[l], p1 = 4.f * sbo[l + 32];
        #pragma unroll 4
        for (int c = 0; c < 64; c++) {
            float t = sos[c];
            p0 += sWoT[c * 64 + l] * t;
            p1 += sWoT[c * 64 + l + 32] * t;
        }
        p0 *= 0.125f; p1 *= 0.125f;
        float* pp = pool + r * 64;
        if (ACCUM) { pp[l] += p0; pp[l + 32] += p1; }
        else       { pp[l] = p0;  pp[l + 32] = p1; }
        __syncwarp();
    }
}

// ---------------- final: out = leaky(Wf.[poolA,poolB]+bf) ------------------
__global__ __launch_bounds__(256)
void final_kernel(const float* __restrict__ Wf, const float* __restrict__ bf,
                  float* __restrict__ out)
{
    int b = blockIdx.x * blockDim.x + threadIdx.x;
    if (b >= BB) return;
    const float4* pa = (const float4*)(g_poolA + b * 64);
    const float4* pb = (const float4*)(g_poolB + b * 64);
    float s = bf[0];
    #pragma unroll
    for (int i = 0; i < 16; i++) {
        float4 v = pa[i];
        float4 wv = *(const float4*)(Wf + 4 * i);
        s += v.x * wv.x + v.y * wv.y + v.z * wv.z + v.w * wv.w;
    }
    #pragma unroll
    for (int i = 0; i < 16; i++) {
        float4 v = pb[i];
        float4 wv = *(const float4*)(Wf + 64 + 4 * i);
        s += v.x * wv.x + v.y * wv.y + v.z * wv.z + v.w * wv.w;
    }
    out[b] = (s > 0.f) ? s : 0.01f * s;
}

// ---------------- launch ---------------------------------------------------
static const int A_SMEM = (16384 + 8192 + 2 * 64 * S1 + 128 * 3 + 64 + 64) * 4;
static const int M_SMEM = (4 * 4096 + 192 + 64 + 8 * WARP_FLOATS) * 4;

extern "C" void kernel_launch(void* const* d_in, const int* in_sizes, int n_in,
                              void* d_out, int out_size)
{
    (void)in_sizes; (void)n_in; (void)out_size;
    const float* x  = (const float*)d_in[0];
    const float* w1 = (const float*)d_in[1];
    const float* b1 = (const float*)d_in[2];
    const float* w2 = (const float*)d_in[3];
    const float* b2 = (const float*)d_in[4];
    const float* w3 = (const float*)d_in[5];
    const float* b3 = (const float*)d_in[6];
    const float* Win_sa = (const float*)d_in[7];
    const float* bin_sa = (const float*)d_in[8];
    const float* Wo_sa  = (const float*)d_in[9];
    const float* bo_sa  = (const float*)d_in[10];
    const float* Win_sb = (const float*)d_in[11];
    const float* bin_sb = (const float*)d_in[12];
    const float* Wo_sb  = (const float*)d_in[13];
    const float* bo_sb  = (const float*)d_in[14];
    const float* Win_ca = (const float*)d_in[15];
    const float* bin_ca = (const float*)d_in[16];
    const float* Wo_ca  = (const float*)d_in[17];
    const float* bo_ca  = (const float*)d_in[18];
    const float* Win_cb = (const float*)d_in[19];
    const float* bin_cb = (const float*)d_in[20];
    const float* Wo_cb  = (const float*)d_in[21];
    const float* bo_cb  = (const float*)d_in[22];
    const float* Wf = (const float*)d_in[23];
    const float* bf = (const float*)d_in[24];
    float* out = (float*)d_out;

    cudaFuncSetAttribute(tok_kernel, cudaFuncAttributeMaxDynamicSharedMemorySize, A_SMEM);
    cudaFuncSetAttribute(mha_kernel<0, 0, false, false>, cudaFuncAttributeMaxDynamicSharedMemorySize, M_SMEM);
    cudaFuncSetAttribute(mha_kernel<4, 4, false, true>,  cudaFuncAttributeMaxDynamicSharedMemorySize, M_SMEM);
    cudaFuncSetAttribute(mha_kernel<0, 4, true,  false>, cudaFuncAttributeMaxDynamicSharedMemorySize, M_SMEM);
    cudaFuncSetAttribute(mha_kernel<4, 0, true,  true>,  cudaFuncAttributeMaxDynamicSharedMemorySize, M_SMEM);

    tok_kernel<<<dim3(18, 8), 512, A_SMEM>>>(x, w1, b1, w2, b2, w3, b3);

    // A_self -> poolA (write), B_self -> poolB (write)
    mha_kernel<0, 0, false, false><<<1184, 256, M_SMEM>>>(Win_sa, bin_sa, Wo_sa, bo_sa);
    mha_kernel<4, 4, false, true ><<<1184, 256, M_SMEM>>>(Win_sb, bin_sb, Wo_sb, bo_sb);
    // A_cross -> poolA (+=), B_cross -> poolB (+=)
    mha_kernel<0, 4, true,  false><<<1184, 256, M_SMEM>>>(Win_ca, bin_ca, Wo_ca, bo_ca);
    mha_kernel<4, 0, true,  true ><<<1184, 256, M_SMEM>>>(Win_cb, bin_cb, Wo_cb, bo_cb);

    final_kernel<<<BB / 256, 256>>>(Wf, bf, out);
}